// round 7
// baseline (speedup 1.0000x reference)
#include <cuda_runtime.h>

typedef unsigned long long u64;

#define NQ     12
#define TPB    256
#define NPARAM 240          // 12 * 4 * 5
#define NLAYER 4
#define FM     0xffffffffu

#define SMEM_BYTES 68704

// ---------------- packed f32x2 complex helpers ----------------
// amplitude packed as u64: lo = Re, hi = Im
__device__ __forceinline__ u64 pk2(float x, float y) {
    u64 r;
    asm("mov.b64 %0, {%1, %2};"
        : "=l"(r) : "r"(__float_as_uint(x)), "r"(__float_as_uint(y)));
    return r;
}
__device__ __forceinline__ void upk2(u64 a, float &x, float &y) {
    unsigned ix, iy;
    asm("mov.b64 {%0, %1}, %2;" : "=r"(ix), "=r"(iy) : "l"(a));
    x = __uint_as_float(ix); y = __uint_as_float(iy);
}
__device__ __forceinline__ u64 swp2(u64 a) {       // (y, x)
    float x, y; upk2(a, x, y); return pk2(y, x);
}
__device__ __forceinline__ u64 ffma2w(u64 a, u64 b, u64 c) {
    u64 r; asm("fma.rn.f32x2 %0, %1, %2, %3;" : "=l"(r) : "l"(a), "l"(b), "l"(c));
    return r;
}
__device__ __forceinline__ u64 fmul2w(u64 a, u64 b) {
    u64 r; asm("mul.rn.f32x2 %0, %1, %2;" : "=l"(r) : "l"(a), "l"(b));
    return r;
}

// Complex gate coefficient, packed: d = (Re,Re), n = (-Im, Im)
struct CG { u64 d, n; };
__device__ __forceinline__ CG mkg(float2 M) {
    CG g; g.d = pk2(M.x, M.x); g.n = pk2(-M.y, M.y); return g;
}
// out = A*v + B*p (complex); vs/ps are swapped copies of v/p
__device__ __forceinline__ u64 axpb2(CG A, u64 v, u64 vs, CG B, u64 p, u64 ps) {
    return ffma2w(A.d, v, ffma2w(A.n, vs, ffma2w(B.d, p, fmul2w(B.n, ps))));
}
// RX on a register pair: cd = (c,c), sm = (s,-s)
// n0 = c*s0 - i s*s1 ; n1 = c*s1 - i s*s0
__device__ __forceinline__ void appRX2(u64 &a, u64 &b, u64 cd, u64 sm) {
    u64 as = swp2(a), bs = swp2(b);
    u64 na = ffma2w(cd, a, fmul2w(sm, bs));
    u64 nb = ffma2w(cd, b, fmul2w(sm, as));
    a = na; b = nb;
}

// ---------------- scalar gate construction ----------------
__device__ __forceinline__ float2 cmulf(float2 a, float2 b) {
    return make_float2(fmaf(a.x, b.x, -a.y * b.y), fmaf(a.x, b.y, a.y * b.x));
}
// M = Rz * Ry * Rx (gates applied in order Rx, Ry, Rz)
__device__ __forceinline__ void build_u(const float* cs, const float* sn, int pi,
        float2 &M00, float2 &M01, float2 &M10, float2 &M11) {
    float cx = cs[pi],     sx = sn[pi];
    float cy = cs[pi + 1], sy = sn[pi + 1];
    float cz = cs[pi + 2], sz = sn[pi + 2];
    float2 A00 = make_float2( cy * cx,  sy * sx);
    float2 A01 = make_float2(-sy * cx, -cy * sx);
    float2 A10 = make_float2( sy * cx, -cy * sx);
    float2 A11 = make_float2( cy * cx, -sy * sx);
    float2 ez  = make_float2(cz, -sz), ezc = make_float2(cz, sz);
    M00 = cmulf(ez,  A00); M01 = cmulf(ez,  A01);
    M10 = cmulf(ezc, A10); M11 = cmulf(ezc, A11);
}
// M <- RX(c,s) * M   (RX applied after M)
__device__ __forceinline__ void fuse_rx(float c, float s,
        float2 &M00, float2 &M01, float2 &M10, float2 &M11) {
    float2 W00 = make_float2(fmaf(c, M00.x,  s * M10.y), fmaf(c, M00.y, -s * M10.x));
    float2 W01 = make_float2(fmaf(c, M01.x,  s * M11.y), fmaf(c, M01.y, -s * M11.x));
    float2 W10 = make_float2(fmaf(c, M10.x,  s * M00.y), fmaf(c, M10.y, -s * M00.x));
    float2 W11 = make_float2(fmaf(c, M11.x,  s * M01.y), fmaf(c, M11.y, -s * M01.x));
    M00 = W00; M01 = W01; M10 = W10; M11 = W11;
}

__global__ void __launch_bounds__(TPB, 2) qfe_kernel(
    const float* __restrict__ params,   // (B, 240)
    const float* __restrict__ inputs,   // (B, 12)
    float* __restrict__ out)            // (B, 36)
{
    extern __shared__ float smem_raw[];
    u64*   bufA = (u64*)smem_raw;               // 4096 u64 = 32 KB
    u64*   bufB = bufA + 4096;                  // 32 KB
    float* cs   = (float*)(bufB + 4096);        // 240
    float* sn   = cs + NPARAM;                  // 240
    float* eic  = sn + NPARAM;                  // 12
    float* eis  = eic + NQ;                     // 12
    float* rbuf = eis + NQ;                     // 288

    const int b = blockIdx.x;
    const int t = threadIdx.x;
    const int lane = t & 31, warp = t >> 5;

    // ---- stage all trig once per block
    if (t < NPARAM) {
        float h = 0.5f * params[b * NPARAM + t];
        sincosf(h, &sn[t], &cs[t]);
    } else if (t < NPARAM + NQ) {
        int i = t - NPARAM;
        float h = 0.5f * inputs[b * NQ + i];
        sincosf(h, &eis[i], &eic[i]);
    }
    __syncthreads();

    // ---- state resident in registers: idx = t | (k<<8); wire w <-> bit (11-w)
    u64 v[16];
    {
        float tp = 1.0f;
        #pragma unroll
        for (int w = 4; w < 12; w++)
            tp *= ((t >> (11 - w)) & 1) ? eis[w] : eic[w];
        #pragma unroll
        for (int k = 0; k < 16; k++) {
            float a = tp;
            #pragma unroll
            for (int w = 0; w < 4; w++)
                a *= ((k >> (3 - w)) & 1) ? eis[w] : eic[w];
            v[k] = pk2(a, 0.0f);
        }
    }

    #pragma unroll 1
    for (int L = 0; L < NLAYER; L++) {
        const int base = 60 * L;

        // ===== U0..U3 on k bits (register-local) =====
        #pragma unroll
        for (int w = 0; w < 4; w++) {
            float2 M00, M01, M10, M11;
            build_u(cs, sn, base + 3 * w, M00, M01, M10, M11);
            CG G00 = mkg(M00), G01 = mkg(M01), G10 = mkg(M10), G11 = mkg(M11);
            int kb = 1 << (3 - w);
            #pragma unroll
            for (int k = 0; k < 16; k++) if (!(k & kb)) {
                u64 s0 = v[k], s1 = v[k | kb];
                u64 s0s = swp2(s0), s1s = swp2(s1);
                v[k]      = axpb2(G00, s0, s0s, G01, s1, s1s);
                v[k | kb] = axpb2(G11, s1, s1s, G10, s0, s0s);
            }
        }
        // ===== F0,F1,F2 (ctrl k(3-i) -> tgt k(2-i), register-local) =====
        #pragma unroll
        for (int i = 0; i < 3; i++) {
            u64 cd = pk2(cs[base + 36 + i], cs[base + 36 + i]);
            u64 sm = pk2(sn[base + 36 + i], -sn[base + 36 + i]);
            int cb = 8 >> i, tb = 4 >> i;
            #pragma unroll
            for (int k = 0; k < 16; k++)
                if ((k & cb) && !(k & tb)) appRX2(v[k], v[k | tb], cd, sm);
        }

        // ===== U4 + F3 : smem exchange axis bit7; F3 cond = k bit0 (per-k) =====
        {
            float2 M00, M01, M10, M11;
            build_u(cs, sn, base + 12, M00, M01, M10, M11);
            float2 W00 = M00, W01 = M01, W10 = M10, W11 = M11;
            fuse_rx(cs[base + 39], sn[base + 39], W00, W01, W10, W11);
            int own = (t >> 7) & 1;
            CG Am = mkg(own ? M11 : M00), Bm = mkg(own ? M10 : M01);
            CG Aw = mkg(own ? W11 : W00), Bw = mkg(own ? W10 : W01);
            #pragma unroll
            for (int k = 0; k < 16; k++) bufA[(k << 8) | t] = v[k];
            __syncthreads();
            int pt = t ^ 128;
            #pragma unroll
            for (int k = 0; k < 16; k++) {
                u64 p = bufA[(k << 8) | pt];
                u64 ps = swp2(p), vs = swp2(v[k]);
                v[k] = (k & 1) ? axpb2(Aw, v[k], vs, Bw, p, ps)
                               : axpb2(Am, v[k], vs, Bm, p, ps);
            }
        }
        // ===== U5 + F4 (cond t bit7): smem axis bit6 =====
        {
            float2 M00, M01, M10, M11;
            build_u(cs, sn, base + 15, M00, M01, M10, M11);
            if (t & 128) fuse_rx(cs[base + 40], sn[base + 40], M00, M01, M10, M11);
            int own = (t >> 6) & 1;
            CG A = mkg(own ? M11 : M00), B = mkg(own ? M10 : M01);
            #pragma unroll
            for (int k = 0; k < 16; k++) bufB[(k << 8) | t] = v[k];
            __syncthreads();
            int pt = t ^ 64;
            #pragma unroll
            for (int k = 0; k < 16; k++) {
                u64 p = bufB[(k << 8) | pt];
                v[k] = axpb2(A, v[k], swp2(v[k]), B, p, swp2(p));
            }
        }
        // ===== U6 + F5 (cond t bit6): smem axis bit5 =====
        {
            float2 M00, M01, M10, M11;
            build_u(cs, sn, base + 18, M00, M01, M10, M11);
            if (t & 64) fuse_rx(cs[base + 41], sn[base + 41], M00, M01, M10, M11);
            int own = (t >> 5) & 1;
            CG A = mkg(own ? M11 : M00), B = mkg(own ? M10 : M01);
            #pragma unroll
            for (int k = 0; k < 16; k++) bufA[(k << 8) | t] = v[k];
            __syncthreads();
            int pt = t ^ 32;
            #pragma unroll
            for (int k = 0; k < 16; k++) {
                u64 p = bufA[(k << 8) | pt];
                v[k] = axpb2(A, v[k], swp2(v[k]), B, p, swp2(p));
            }
        }
        // ===== U7..U11 + F6..F10 : shfl, axis m=1<<(11-w), cond bit = m<<1 =====
        #pragma unroll
        for (int w = 7; w < 12; w++) {
            const int m = 1 << (11 - w);
            float2 M00, M01, M10, M11;
            build_u(cs, sn, base + 3 * w, M00, M01, M10, M11);
            if (t & (m << 1))
                fuse_rx(cs[base + 36 + w - 1], sn[base + 36 + w - 1], M00, M01, M10, M11);
            int own = (t & m) ? 1 : 0;
            CG A = mkg(own ? M11 : M00), B = mkg(own ? M10 : M01);
            #pragma unroll
            for (int k = 0; k < 16; k++) {
                float x, y; upk2(v[k], x, y);
                float px = __shfl_xor_sync(FM, x, m);
                float py = __shfl_xor_sync(FM, y, m);
                v[k] = axpb2(A, v[k], pk2(y, x), B, pk2(px, py), pk2(py, px));
            }
        }
        // ===== F11: ctrl t bit0, tgt k bit3 (register-local) =====
        {
            u64 cd = pk2(cs[base + 47], cs[base + 47]);
            u64 sm = pk2(sn[base + 47], -sn[base + 47]);
            if (t & 1) {
                #pragma unroll
                for (int k = 0; k < 8; k++) appRX2(v[k], v[k | 8], cd, sm);
            }
        }
        // ===== B11..B8: shfl CRX, axis m=1<<(12-i), cond bit = m>>1 =====
        #pragma unroll
        for (int i = 11; i >= 8; i--) {
            const int m = 1 << (12 - i);
            u64 cd = pk2(cs[base + 48 + (11 - i)], cs[base + 48 + (11 - i)]);
            u64 sm = pk2(sn[base + 48 + (11 - i)], -sn[base + 48 + (11 - i)]);
            int cond = t & (m >> 1);
            #pragma unroll
            for (int k = 0; k < 16; k++) {
                float x, y; upk2(v[k], x, y);
                float px = __shfl_xor_sync(FM, x, m);
                float py = __shfl_xor_sync(FM, y, m);
                u64 nv = ffma2w(cd, v[k], fmul2w(sm, pk2(py, px)));
                if (cond) v[k] = nv;
            }
        }
        // ===== B7: smem axis bit5, cond t bit4 =====
        {
            u64 cd = pk2(cs[base + 52], cs[base + 52]);
            u64 sm = pk2(sn[base + 52], -sn[base + 52]);
            #pragma unroll
            for (int k = 0; k < 16; k++) bufB[(k << 8) | t] = v[k];
            __syncthreads();
            if (t & 16) {
                int pt = t ^ 32;
                #pragma unroll
                for (int k = 0; k < 16; k++) {
                    u64 p = bufB[(k << 8) | pt];
                    v[k] = ffma2w(cd, v[k], fmul2w(sm, swp2(p)));
                }
            }
        }
        // ===== B6: smem axis bit6, cond t bit5 =====
        {
            u64 cd = pk2(cs[base + 53], cs[base + 53]);
            u64 sm = pk2(sn[base + 53], -sn[base + 53]);
            #pragma unroll
            for (int k = 0; k < 16; k++) bufA[(k << 8) | t] = v[k];
            __syncthreads();
            if (t & 32) {
                int pt = t ^ 64;
                #pragma unroll
                for (int k = 0; k < 16; k++) {
                    u64 p = bufA[(k << 8) | pt];
                    v[k] = ffma2w(cd, v[k], fmul2w(sm, swp2(p)));
                }
            }
        }
        // ===== B5: smem axis bit7, cond t bit6 =====
        {
            u64 cd = pk2(cs[base + 54], cs[base + 54]);
            u64 sm = pk2(sn[base + 54], -sn[base + 54]);
            #pragma unroll
            for (int k = 0; k < 16; k++) bufB[(k << 8) | t] = v[k];
            __syncthreads();
            if (t & 64) {
                int pt = t ^ 128;
                #pragma unroll
                for (int k = 0; k < 16; k++) {
                    u64 p = bufB[(k << 8) | pt];
                    v[k] = ffma2w(cd, v[k], fmul2w(sm, swp2(p)));
                }
            }
        }
        // ===== B4: ctrl t bit7, tgt k bit0 (register-local) =====
        {
            u64 cd = pk2(cs[base + 55], cs[base + 55]);
            u64 sm = pk2(sn[base + 55], -sn[base + 55]);
            if (t & 128) {
                #pragma unroll
                for (int k = 0; k < 16; k += 2) appRX2(v[k], v[k | 1], cd, sm);
            }
        }
        // ===== B3,B2,B1: ctrl k(j) -> tgt k(j+1) (register-local) =====
        #pragma unroll
        for (int j = 0; j < 3; j++) {
            u64 cd = pk2(cs[base + 56 + j], cs[base + 56 + j]);
            u64 sm = pk2(sn[base + 56 + j], -sn[base + 56 + j]);
            int cb = 1 << j, tb = 2 << j;
            #pragma unroll
            for (int k = 0; k < 16; k++)
                if ((k & cb) && !(k & tb)) appRX2(v[k], v[k | tb], cd, sm);
        }
        // ===== B0: ctrl k bit3, tgt lane bit0 (shfl, k>=8 only) =====
        {
            u64 cd = pk2(cs[base + 59], cs[base + 59]);
            u64 sm = pk2(sn[base + 59], -sn[base + 59]);
            #pragma unroll
            for (int k = 8; k < 16; k++) {
                float x, y; upk2(v[k], x, y);
                float px = __shfl_xor_sync(FM, x, 1);
                float py = __shfl_xor_sync(FM, y, 1);
                v[k] = ffma2w(cd, v[k], fmul2w(sm, pk2(py, px)));
            }
        }
    }

    // ================= expectations =================
    // dump state once for warp-axis wires 4-6
    #pragma unroll
    for (int k = 0; k < 16; k++) bufA[(k << 8) | t] = v[k];
    __syncthreads();

    float vx[16], vy[16], nv[16], S = 0.0f;
    #pragma unroll
    for (int k = 0; k < 16; k++) {
        upk2(v[k], vx[k], vy[k]);
        nv[k] = fmaf(vx[k], vx[k], vy[k] * vy[k]);
        S += nv[k];
    }

    // wires 0-3: k-bit pairs (register-local)
    #pragma unroll
    for (int w = 0; w < 4; w++) {
        int kb = 1 << (3 - w);
        float rr = 0.f, ri = 0.f, rz = 0.f;
        #pragma unroll
        for (int k = 0; k < 16; k++) {
            if (!(k & kb)) {
                int k1 = k | kb;
                rr = fmaf(vx[k], vx[k1], fmaf( vy[k], vy[k1], rr));
                ri = fmaf(vx[k], vy[k1], fmaf(-vy[k], vx[k1], ri));
            }
            rz += (k & kb) ? -nv[k] : nv[k];
        }
        #pragma unroll
        for (int off = 16; off; off >>= 1) {
            rr += __shfl_down_sync(FM, rr, off);
            ri += __shfl_down_sync(FM, ri, off);
            rz += __shfl_down_sync(FM, rz, off);
        }
        if (lane == 0) {
            rbuf[w * 8 + warp]       = rr;
            rbuf[96 + w * 8 + warp]  = ri;
            rbuf[192 + w * 8 + warp] = rz;
        }
    }

    // wires 4-6: warp-bit pairs (partner from bufA; own-bit==0 threads only)
    #pragma unroll
    for (int w = 4; w < 7; w++) {
        int pb = 11 - w;
        int own = (t >> pb) & 1;
        float rr = 0.f, ri = 0.f;
        if (!own) {
            int pt = t | (1 << pb);
            #pragma unroll
            for (int k = 0; k < 16; k++) {
                float cxv, cyv; upk2(bufA[(k << 8) | pt], cxv, cyv);
                rr = fmaf(vx[k], cxv, fmaf( vy[k], cyv, rr));
                ri = fmaf(vx[k], cyv, fmaf(-vy[k], cxv, ri));
            }
        }
        float rz = own ? -S : S;
        #pragma unroll
        for (int off = 16; off; off >>= 1) {
            rr += __shfl_down_sync(FM, rr, off);
            ri += __shfl_down_sync(FM, ri, off);
            rz += __shfl_down_sync(FM, rz, off);
        }
        if (lane == 0) {
            rbuf[w * 8 + warp]       = rr;
            rbuf[96 + w * 8 + warp]  = ri;
            rbuf[192 + w * 8 + warp] = rz;
        }
    }

    // wires 7-11: lane-bit pairs (shfl partner)
    #pragma unroll
    for (int w = 7; w < 12; w++) {
        int pb = 11 - w;
        int m = 1 << pb;
        int own = (t >> pb) & 1;
        float rr = 0.f, ri = 0.f;
        #pragma unroll
        for (int k = 0; k < 16; k++) {
            float px = __shfl_xor_sync(FM, vx[k], m);
            float py = __shfl_xor_sync(FM, vy[k], m);
            if (!own) {
                rr = fmaf(vx[k], px, fmaf( vy[k], py, rr));
                ri = fmaf(vx[k], py, fmaf(-vy[k], px, ri));
            }
        }
        float rz = own ? -S : S;
        #pragma unroll
        for (int off = 16; off; off >>= 1) {
            rr += __shfl_down_sync(FM, rr, off);
            ri += __shfl_down_sync(FM, ri, off);
            rz += __shfl_down_sync(FM, rz, off);
        }
        if (lane == 0) {
            rbuf[w * 8 + warp]       = rr;
            rbuf[96 + w * 8 + warp]  = ri;
            rbuf[192 + w * 8 + warp] = rz;
        }
    }

    __syncthreads();
    if (t < 36) {
        float a = 0.f;
        #pragma unroll
        for (int q = 0; q < 8; q++) a += rbuf[t * 8 + q];
        out[b * 36 + t] = (t < 24) ? 2.0f * a : a;
    }
}

extern "C" void kernel_launch(void* const* d_in, const int* in_sizes, int n_in,
                              void* d_out, int out_size) {
    const float* params = (const float*)d_in[0];   // (B, 240) float32
    const float* inputs = (const float*)d_in[1];   // (B, 12)  float32
    float* out = (float*)d_out;                    // (B, 36)  float32
    int B = in_sizes[0] / NPARAM;
    static bool attr_set = false;
    if (!attr_set) {
        cudaFuncSetAttribute(qfe_kernel,
                             cudaFuncAttributeMaxDynamicSharedMemorySize,
                             SMEM_BYTES);
        attr_set = true;
    }
    qfe_kernel<<<B, TPB, SMEM_BYTES>>>(params, inputs, out);
}